// round 12
// baseline (speedup 1.0000x reference)
#include <cuda_runtime.h>

// SNN + STDP scan, 256 steps, 784 inputs, 512 neurons.
// R11: NEURON-PAIR ILP. 8 warps (wings) cooperate on TWO neurons; each lane
// holds the same f4 chunk of both neurons' W rows. Two independent butterfly/
// LIF/update chains per warp interleave (ILP covers latency without R10's x7
// per-warp overhead). x chunks and the pre-trace are neuron-independent ->
// loaded/updated ONCE per pair. 512-thread blocks, 128 blocks, 2 groups of
// 8 warps, per-group named barrier (256 threads).
// Kept: packed fma.rn.f32x2, fused next-step dot, __stcs streaming stores.

namespace {
constexpr int   T_STEPS = 256;
constexpr int   D_IN    = 784;
constexpr int   N_NEUR  = 512;
constexpr int   CHUNKS  = D_IN / 4;   // 196 float4 per row
constexpr int   WPG     = 8;          // wings (warps) per group
constexpr int   GPB     = 2;          // groups per block
constexpr int   NTHREADS = GPB * WPG * 32;   // 512
constexpr float ALPHA      = 0.9f;
constexpr float BETA       = 0.8f;
constexpr float THRESHOLD  = 1.0f;
constexpr float BETA_PLUS  = 0.9f;
constexpr float BETA_MINUS = 0.9f;
constexpr float A_PLUS     = 0.008f;
constexpr float A_MINUS    = 0.0066f;
}

using u64 = unsigned long long;

__device__ __forceinline__ u64 pk2(float lo, float hi) {
    u64 r; asm("mov.b64 %0, {%1, %2};" : "=l"(r) : "f"(lo), "f"(hi)); return r;
}
__device__ __forceinline__ void upk2(u64 v, float& lo, float& hi) {
    asm("mov.b64 {%0, %1}, %2;" : "=f"(lo), "=f"(hi) : "l"(v));
}
__device__ __forceinline__ u64 ffma2(u64 a, u64 b, u64 c) {
    u64 d; asm("fma.rn.f32x2 %0, %1, %2, %3;" : "=l"(d) : "l"(a), "l"(b), "l"(c));
    return d;
}
__device__ __forceinline__ void group_bar(int id) {
    asm volatile("bar.sync %0, %1;" :: "r"(id), "n"(WPG * 32) : "memory");
}
__device__ __forceinline__ void stg_cs_v2b64(void* p, u64 a, u64 b) {
    asm volatile("st.global.cs.v2.b64 [%0], {%1, %2};" :: "l"(p), "l"(a), "l"(b) : "memory");
}

__global__ __launch_bounds__(NTHREADS, 1)
void snn_pair(const float* __restrict__ image,
              const float* __restrict__ W0,
              float* __restrict__ out)
{
    const int tid  = threadIdx.x;
    const int lane = tid & 31;
    const int warp = tid >> 5;            // 0..15
    const int grp  = warp >> 3;           // 0..1
    const int wing = warp & 7;            // 0..7
    const int n0   = blockIdx.x * (GPB * 2) + grp * 2;   // even neuron
    const int n1   = n0 + 1;
    const int barid = grp + 1;

    const int  c     = (wing << 5) + lane;   // chunk id, 0..255
    const bool valid = (c < CHUNKS);

    const float4 f4z = make_float4(0.f, 0.f, 0.f, 0.f);
    const u64 AP2 = pk2(A_PLUS, A_PLUS);
    const u64 BP2 = pk2(BETA_PLUS, BETA_PLUS);

    u64 wA01, wA23, wB01, wB23;           // W chunks, both neurons
    u64 pre01 = 0ull, pre23 = 0ull;       // pre-trace: shared (x-only state)
    u64 xc01, xc23, xn01, xn23;           // x_t, x_{t+1} (shared)

    {   // load W chunks + x_0, x_1
        const float4* wra = reinterpret_cast<const float4*>(W0) + (size_t)n0 * CHUNKS;
        const float4* wrb = reinterpret_cast<const float4*>(W0) + (size_t)n1 * CHUNKS;
        const float4* xr  = reinterpret_cast<const float4*>(image);
        float4 ta = valid ? __ldg(wra + c) : f4z;
        float4 tb = valid ? __ldg(wrb + c) : f4z;
        float4 a0 = valid ? __ldg(xr + c) : f4z;
        float4 b0 = valid ? __ldg(xr + CHUNKS + c) : f4z;
        wA01 = pk2(ta.x, ta.y);  wA23 = pk2(ta.z, ta.w);
        wB01 = pk2(tb.x, tb.y);  wB23 = pk2(tb.z, tb.w);
        xc01 = pk2(a0.x, a0.y);  xc23 = pk2(a0.z, a0.w);
        xn01 = pk2(b0.x, b0.y);  xn23 = pk2(b0.z, b0.w);
    }
    const float4* xpf = reinterpret_cast<const float4*>(image) + 2 * (size_t)CHUNKS;

    // ---- prologue: per-lane partials of W0 . x_0 for both neurons ----
    float pA, pB;
    {
        u64 mA = ffma2(wA01, xc01, 0ull); mA = ffma2(wA23, xc23, mA);
        u64 mB = ffma2(wB01, xc01, 0ull); mB = ffma2(wB23, xc23, mB);
        float aa, ab, ba, bb;
        upk2(mA, aa, ab); upk2(mB, ba, bb);
        pA = aa + ab;  pB = ba + bb;
    }

    // partials: [buf][group][neuron(2)][wing(8)]
    __shared__ float part[2][GPB][2][WPG];

    float synA = 0.f, memA = 0.f, spkApv = 0.f, postA = 0.f;
    float synB = 0.f, memB = 0.f, spkBpv = 0.f, postB = 0.f;

    float* __restrict__ spkrec  = out + (size_t)T_STEPS * N_NEUR * D_IN;
    float* __restrict__ memrec  = spkrec  + T_STEPS * N_NEUR;
    float* __restrict__ synrec  = memrec  + T_STEPS * N_NEUR;
    float* __restrict__ postrec = synrec  + T_STEPS * N_NEUR;

    float4* wptrA = reinterpret_cast<float4*>(out) + (size_t)n0 * CHUNKS;
    float4* wptrB = reinterpret_cast<float4*>(out) + (size_t)n1 * CHUNKS;
    int sidx = n0;

    #pragma unroll 2
    for (int t = 0; t < T_STEPS; ++t) {
        const int buf = t & 1;

        // ---- two interleaved butterflies (independent chains) ----
        float rA = pA, rB = pB;
        #pragma unroll
        for (int s = 1; s < 32; s <<= 1) {
            rA += __shfl_xor_sync(0xffffffffu, rA, s);
            rB += __shfl_xor_sync(0xffffffffu, rB, s);
        }
        if (lane == 0) {
            part[buf][grp][0][wing] = rA;
            part[buf][grp][1][wing] = rB;
        }
        group_bar(barid);

        // ---- I per neuron: 2 LDS.128 + 7 adds each ----
        float IA, IB;
        {
            const float4 a0 = *reinterpret_cast<const float4*>(&part[buf][grp][0][0]);
            const float4 a1 = *reinterpret_cast<const float4*>(&part[buf][grp][0][4]);
            const float4 b0 = *reinterpret_cast<const float4*>(&part[buf][grp][1][0]);
            const float4 b1 = *reinterpret_cast<const float4*>(&part[buf][grp][1][4]);
            IA = ((a0.x + a0.y) + (a0.z + a0.w)) + ((a1.x + a1.y) + (a1.z + a1.w));
            IB = ((b0.x + b0.y) + (b0.z + b0.w)) + ((b1.x + b1.y) + (b1.z + b1.w));
        }

        // ---- two independent LIF chains ----
        synA = fmaf(ALPHA, synA, IA);
        synB = fmaf(ALPHA, synB, IB);
        memA = fmaf(BETA, memA, synA) - spkApv * THRESHOLD;
        memB = fmaf(BETA, memB, synB) - spkBpv * THRESHOLD;
        const float spkA = (memA > THRESHOLD) ? 1.0f : 0.0f;
        const float spkB = (memB > THRESHOLD) ? 1.0f : 0.0f;
        postA = fmaf(BETA_MINUS, postA, spkA);
        postB = fmaf(BETA_MINUS, postB, spkB);

        const u64   apA2 = pk2(A_PLUS * spkA, A_PLUS * spkA);
        const u64   apB2 = pk2(A_PLUS * spkB, A_PLUS * spkB);
        const float amA  = -(A_MINUS * postA);
        const float amB  = -(A_MINUS * postB);

        // ---- updates (shared xc), stores, fused next dots ----
        float xx, xy, xz, xw;
        upk2(xc01, xx, xy); upk2(xc23, xz, xw);
        {   // neuron A
            const u64 tA01 = ffma2(apA2, pre01, wA01);
            const u64 tA23 = ffma2(apA2, pre23, wA23);
            float t0, t1, t2, t3;
            upk2(tA01, t0, t1); upk2(tA23, t2, t3);
            wA01 = pk2(__saturatef(fmaf(amA, xx, t0)),
                       __saturatef(fmaf(amA, xy, t1)));
            wA23 = pk2(__saturatef(fmaf(amA, xz, t2)),
                       __saturatef(fmaf(amA, xw, t3)));
            if (valid) stg_cs_v2b64(wptrA + c, wA01, wA23);
            u64 d = ffma2(wA01, xn01, 0ull); d = ffma2(wA23, xn23, d);
            float da, db_; upk2(d, da, db_);
            pA = da + db_;
        }
        {   // neuron B
            const u64 tB01 = ffma2(apB2, pre01, wB01);
            const u64 tB23 = ffma2(apB2, pre23, wB23);
            float t0, t1, t2, t3;
            upk2(tB01, t0, t1); upk2(tB23, t2, t3);
            wB01 = pk2(__saturatef(fmaf(amB, xx, t0)),
                       __saturatef(fmaf(amB, xy, t1)));
            wB23 = pk2(__saturatef(fmaf(amB, xz, t2)),
                       __saturatef(fmaf(amB, xw, t3)));
            if (valid) stg_cs_v2b64(wptrB + c, wB01, wB23);
            u64 d = ffma2(wB01, xn01, 0ull); d = ffma2(wB23, xn23, d);
            float da, db_; upk2(d, da, db_);
            pB = da + db_;
        }

        // ---- pre-trace recurrence: ONCE for the pair ----
        pre01 = ffma2(BP2, pre01, xc01);
        pre23 = ffma2(BP2, pre23, xc23);

        // ---- rotate x, prefetch x_{t+2} (shared) ----
        xc01 = xn01; xc23 = xn23;
        if (valid && (t + 2 < T_STEPS)) {
            float4 xt = __ldg(xpf + c);
            xn01 = pk2(xt.x, xt.y);
            xn23 = pk2(xt.z, xt.w);
        }

        // ---- scalar records: lane0 -> neuron A, lane1 -> neuron B ----
        if (wing == 0 && lane < 2) {
            const int idx = sidx + lane;             // n0, n1 adjacent
            spkrec[idx]  = (lane == 0) ? spkA : spkB;
            memrec[idx]  = (lane == 0) ? memA : memB;
            synrec[idx]  = (lane == 0) ? synA : synB;
            postrec[idx] = (lane == 0) ? postA : postB;
        }

        spkApv = spkA;  spkBpv = spkB;
        wptrA += (size_t)N_NEUR * CHUNKS;
        wptrB += (size_t)N_NEUR * CHUNKS;
        xpf   += CHUNKS;
        sidx  += N_NEUR;
    }
}

extern "C" void kernel_launch(void* const* d_in, const int* in_sizes, int n_in,
                              void* d_out, int out_size)
{
    const float* image = (const float*)d_in[0];  // [256, 784] f32
    const float* W     = (const float*)d_in[1];  // [512, 784] f32
    float* out = (float*)d_out;
    (void)in_sizes; (void)n_in; (void)out_size;
    snn_pair<<<N_NEUR / (GPB * 2), NTHREADS>>>(image, W, out);
}

// round 15
// speedup vs baseline: 1.0607x; 1.0607x over previous
#include <cuda_runtime.h>

// SNN + STDP scan, 256 steps, 784 inputs, 512 neurons.
// R12 = R7 (best: 88.2us) + three additive chain cuts, no restructuring:
//  (1) reduction: 3-shfl butterfly -> 4 octet-partials per wing to smem
//      (pre-barrier chain -52cyc; post-barrier +3 LDS.128 + adds, issue-idle)
//  (2) LIF tail precomputed pre-barrier: base/synb + both post/am candidates
//      (post-barrier chain: I -> 1 FADD -> setp -> selp)
//  (3) triple-buffered x (prefetch x_{t+3}): no L2-latency exposure in the
//      fused next-step dot.
// Kept from R7: 4 warps/neuron, 4 neurons/block, packed fma.rn.f32x2,
// per-neuron named barrier, fused next-step dot, __stcs streaming stores.

namespace {
constexpr int   T_STEPS = 256;
constexpr int   D_IN    = 784;
constexpr int   N_NEUR  = 512;
constexpr int   CHUNKS  = D_IN / 4;   // 196 float4 per row
constexpr int   WPN     = 4;
constexpr int   NPB     = 4;
constexpr int   KMAX    = 2;
constexpr float ALPHA      = 0.9f;
constexpr float BETA       = 0.8f;
constexpr float THRESHOLD  = 1.0f;
constexpr float BETA_PLUS  = 0.9f;
constexpr float BETA_MINUS = 0.9f;
constexpr float A_PLUS     = 0.008f;
constexpr float A_MINUS    = 0.0066f;
}

using u64 = unsigned long long;

__device__ __forceinline__ u64 pk2(float lo, float hi) {
    u64 r; asm("mov.b64 %0, {%1, %2};" : "=l"(r) : "f"(lo), "f"(hi)); return r;
}
__device__ __forceinline__ void upk2(u64 v, float& lo, float& hi) {
    asm("mov.b64 {%0, %1}, %2;" : "=f"(lo), "=f"(hi) : "l"(v));
}
__device__ __forceinline__ u64 ffma2(u64 a, u64 b, u64 c) {
    u64 d; asm("fma.rn.f32x2 %0, %1, %2, %3;" : "=l"(d) : "l"(a), "l"(b), "l"(c));
    return d;
}
__device__ __forceinline__ void neuron_bar(int id) {
    asm volatile("bar.sync %0, 128;" :: "r"(id) : "memory");
}
__device__ __forceinline__ void stg_cs_v2b64(void* p, u64 a, u64 b) {
    asm volatile("st.global.cs.v2.b64 [%0], {%1, %2};" :: "l"(p), "l"(a), "l"(b) : "memory");
}

__global__ __launch_bounds__(512, 1)
void snn_chain(const float* __restrict__ image,
               const float* __restrict__ W0,
               float* __restrict__ out)
{
    const int tid   = threadIdx.x;
    const int lane  = tid & 31;
    const int warp  = tid >> 5;
    const int group = warp >> 2;         // neuron slot, 0..3
    const int wing  = warp & 3;
    const int n     = blockIdx.x * NPB + group;
    const int barid = group + 1;

    const int  c0  = (wing << 5) + lane;
    const int  c1  = c0 + 128;
    const bool k1v = (c1 < CHUNKS);

    const float4 f4z = make_float4(0.f, 0.f, 0.f, 0.f);
    const u64 AP2 = pk2(A_PLUS, A_PLUS);
    const u64 BP2 = pk2(BETA_PLUS, BETA_PLUS);

    u64 w01[KMAX], w23[KMAX], pre01[KMAX], pre23[KMAX];
    u64 xc01[KMAX], xc23[KMAX], xn01[KMAX], xn23[KMAX], x201[KMAX], x223[KMAX];

    {   // load W row (packed)
        const float4* wrow = reinterpret_cast<const float4*>(W0) + (size_t)n * CHUNKS;
        float4 t0 = __ldg(wrow + c0);
        float4 t1 = k1v ? __ldg(wrow + c1) : f4z;
        w01[0] = pk2(t0.x, t0.y);  w23[0] = pk2(t0.z, t0.w);
        w01[1] = pk2(t1.x, t1.y);  w23[1] = pk2(t1.z, t1.w);
    }
    #pragma unroll
    for (int k = 0; k < KMAX; ++k) { pre01[k] = 0ull; pre23[k] = 0ull; }

    {   // prefetch x_0, x_1, x_2
        const float4* xr = reinterpret_cast<const float4*>(image);
        float4 a0 = __ldg(xr + c0);
        float4 a1 = k1v ? __ldg(xr + c1) : f4z;
        float4 b0 = __ldg(xr + CHUNKS + c0);
        float4 b1 = k1v ? __ldg(xr + CHUNKS + c1) : f4z;
        float4 e0 = __ldg(xr + 2 * CHUNKS + c0);
        float4 e1 = k1v ? __ldg(xr + 2 * CHUNKS + c1) : f4z;
        xc01[0] = pk2(a0.x, a0.y); xc23[0] = pk2(a0.z, a0.w);
        xc01[1] = pk2(a1.x, a1.y); xc23[1] = pk2(a1.z, a1.w);
        xn01[0] = pk2(b0.x, b0.y); xn23[0] = pk2(b0.z, b0.w);
        xn01[1] = pk2(b1.x, b1.y); xn23[1] = pk2(b1.z, b1.w);
        x201[0] = pk2(e0.x, e0.y); x223[0] = pk2(e0.z, e0.w);
        x201[1] = pk2(e1.x, e1.y); x223[1] = pk2(e1.z, e1.w);
    }
    const float4* xpf = reinterpret_cast<const float4*>(image) + 3 * (size_t)CHUNKS;

    // ---- prologue: per-lane partial of W0 . x_0 ----
    float p;
    {
        u64 m01 = ffma2(w01[0], xc01[0], 0ull);
        m01     = ffma2(w01[1], xc01[1], m01);
        u64 m23 = ffma2(w23[0], xc23[0], 0ull);
        m23     = ffma2(w23[1], xc23[1], m23);
        float aa, ab, ac, ad;
        upk2(m01, aa, ab); upk2(m23, ac, ad);
        p = (aa + ab) + (ac + ad);
    }

    // 16 octet-partials per neuron (4 wings x 4), double buffered.
    __shared__ float part[2][NPB][16];

    float syn = 0.f, mem = 0.f, spk_prev = 0.f, post = 0.f;

    float* __restrict__ spkrec  = out + (size_t)T_STEPS * N_NEUR * D_IN;
    float* __restrict__ memrec  = spkrec  + T_STEPS * N_NEUR;
    float* __restrict__ synrec  = memrec  + T_STEPS * N_NEUR;
    float* __restrict__ postrec = synrec  + T_STEPS * N_NEUR;

    float4* wptr = reinterpret_cast<float4*>(out) + (size_t)n * CHUNKS;
    int sidx = n;

    #pragma unroll 2
    for (int t = 0; t < T_STEPS; ++t) {
        const int buf = t & 1;

        // ---- (1) 3-shfl butterfly -> octet partials on lanes 0,8,16,24 ----
        float r = p;
        r += __shfl_xor_sync(0xffffffffu, r, 1);
        r += __shfl_xor_sync(0xffffffffu, r, 2);
        r += __shfl_xor_sync(0xffffffffu, r, 4);
        if ((lane & 7) == 0)
            part[buf][group][(wing << 2) + (lane >> 3)] = r;

        // ---- (3) issue prefetch of x_{t+3} into temps (drains over bar) ----
        float4 pf0 = f4z, pf1 = f4z;
        if (t + 3 < T_STEPS) {
            pf0 = __ldg(xpf + c0);
            if (k1v) pf1 = __ldg(xpf + c1);
        }

        // ---- (2) pre-barrier LIF precompute (off the critical chain) ----
        const float synb  = ALPHA * syn;
        const float base  = fmaf(BETA, mem, synb - spk_prev * THRESHOLD);
        const float post0 = BETA_MINUS * post;
        const float post1 = fmaf(BETA_MINUS, post, 1.0f);
        const float am0   = -(A_MINUS * post0);
        const float am1   = -(A_MINUS * post1);

        neuron_bar(barid);

        // ---- I: 4 broadcast LDS.128 + 15 adds ----
        const float* pb = part[buf][group];
        const float4 q0 = *reinterpret_cast<const float4*>(pb + 0);
        const float4 q1 = *reinterpret_cast<const float4*>(pb + 4);
        const float4 q2 = *reinterpret_cast<const float4*>(pb + 8);
        const float4 q3 = *reinterpret_cast<const float4*>(pb + 12);
        const float s0 = (q0.x + q0.y) + (q0.z + q0.w);
        const float s1 = (q1.x + q1.y) + (q1.z + q1.w);
        const float s2 = (q2.x + q2.y) + (q2.z + q2.w);
        const float s3 = (q3.x + q3.y) + (q3.z + q3.w);
        const float I  = (s0 + s1) + (s2 + s3);

        // ---- short post-barrier LIF: 2 FADD -> setp -> selects ----
        syn = synb + I;
        mem = base + I;
        const bool  spkb = (mem > THRESHOLD);
        const float spk  = spkb ? 1.0f : 0.0f;
        post = spkb ? post1 : post0;
        const float am   = spkb ? am1 : am0;
        const u64   ap2  = spkb ? AP2 : 0ull;

        // ---- STDP update + store W_rec[t]; fused next dot ----
        u64 da = 0ull, db = 0ull;
        #pragma unroll
        for (int k = 0; k < KMAX; ++k) {
            const bool act = (k == 0) || k1v;
            const int  c   = (k == 0) ? c0 : c1;

            const u64 t01 = ffma2(ap2, pre01[k], w01[k]);
            const u64 t23 = ffma2(ap2, pre23[k], w23[k]);
            float tx, ty, tz, tw, xx, xy, xz, xw;
            upk2(t01, tx, ty); upk2(t23, tz, tw);
            upk2(xc01[k], xx, xy); upk2(xc23[k], xz, xw);
            w01[k] = pk2(__saturatef(fmaf(am, xx, tx)),
                         __saturatef(fmaf(am, xy, ty)));
            w23[k] = pk2(__saturatef(fmaf(am, xz, tz)),
                         __saturatef(fmaf(am, xw, tw)));
            if (act) stg_cs_v2b64(wptr + c, w01[k], w23[k]);

            // fused dot for step t+1: W(t) . x_{t+1}
            da = ffma2(w01[k], xn01[k], da);
            db = ffma2(w23[k], xn23[k], db);

            // pre-trace recurrence (uses x_t)
            pre01[k] = ffma2(BP2, pre01[k], xc01[k]);
            pre23[k] = ffma2(BP2, pre23[k], xc23[k]);

            // rotate triple buffer; commit prefetch temps
            xc01[k] = xn01[k]; xc23[k] = xn23[k];
            xn01[k] = x201[k]; xn23[k] = x223[k];
        }
        x201[0] = pk2(pf0.x, pf0.y); x223[0] = pk2(pf0.z, pf0.w);
        x201[1] = pk2(pf1.x, pf1.y); x223[1] = pk2(pf1.z, pf1.w);
        {
            float aa, ab, ac, ad;
            upk2(da, aa, ab); upk2(db, ac, ad);
            p = (aa + ab) + (ac + ad);
        }

        // ---- scalar records (one thread per neuron) ----
        if (wing == 0 && lane == 0) {
            spkrec[sidx]  = spk;
            memrec[sidx]  = mem;
            synrec[sidx]  = syn;
            postrec[sidx] = post;
        }

        spk_prev = spk;
        wptr += (size_t)N_NEUR * CHUNKS;
        xpf  += CHUNKS;
        sidx += N_NEUR;
    }
}

extern "C" void kernel_launch(void* const* d_in, const int* in_sizes, int n_in,
                              void* d_out, int out_size)
{
    const float* image = (const float*)d_in[0];  // [256, 784] f32
    const float* W     = (const float*)d_in[1];  // [512, 784] f32
    float* out = (float*)d_out;
    (void)in_sizes; (void)n_in; (void)out_size;
    snn_chain<<<N_NEUR / NPB, NPB * WPN * 32>>>(image, W, out);
}

// round 17
// speedup vs baseline: 1.0983x; 1.0355x over previous
#include <cuda_runtime.h>

// SNN + STDP scan, 256 steps, 784 inputs, 512 neurons.
// R15 = R7 (best: 88.2us, 62 regs) + ONLY two clean chain cuts (R12 bundled
// these with a reg-bloating triple-buffer that confounded the experiment):
//  (1) 3-shfl butterfly -> 4 octet-partials per wing (pre-bar chain -52cyc);
//      I = 4 independent broadcast LDS.128 + add tree post-barrier.
//  (2) LIF tail hoisted pre-barrier: synb, base(=beta*mem+synb-spk_prev),
//      post0/post1, am0/am1. Post-barrier: I -> 1 FADD -> setp -> selects.
// Everything else byte-for-byte R7: 4 warps/neuron, 4 neurons/block, packed
// fma.rn.f32x2, per-neuron named barrier, fused next-step dot, double-
// buffered x with unroll-2 rename, __stcs streaming W_rec stores.

namespace {
constexpr int   T_STEPS = 256;
constexpr int   D_IN    = 784;
constexpr int   N_NEUR  = 512;
constexpr int   CHUNKS  = D_IN / 4;   // 196 float4 per row
constexpr int   WPN     = 4;
constexpr int   NPB     = 4;
constexpr int   KMAX    = 2;
constexpr float ALPHA      = 0.9f;
constexpr float BETA       = 0.8f;
constexpr float THRESHOLD  = 1.0f;
constexpr float BETA_PLUS  = 0.9f;
constexpr float BETA_MINUS = 0.9f;
constexpr float A_PLUS     = 0.008f;
constexpr float A_MINUS    = 0.0066f;
}

using u64 = unsigned long long;

__device__ __forceinline__ u64 pk2(float lo, float hi) {
    u64 r; asm("mov.b64 %0, {%1, %2};" : "=l"(r) : "f"(lo), "f"(hi)); return r;
}
__device__ __forceinline__ void upk2(u64 v, float& lo, float& hi) {
    asm("mov.b64 {%0, %1}, %2;" : "=f"(lo), "=f"(hi) : "l"(v));
}
__device__ __forceinline__ u64 ffma2(u64 a, u64 b, u64 c) {
    u64 d; asm("fma.rn.f32x2 %0, %1, %2, %3;" : "=l"(d) : "l"(a), "l"(b), "l"(c));
    return d;
}
__device__ __forceinline__ void neuron_bar(int id) {
    asm volatile("bar.sync %0, 128;" :: "r"(id) : "memory");
}
__device__ __forceinline__ void stg_cs_v2b64(void* p, u64 a, u64 b) {
    asm volatile("st.global.cs.v2.b64 [%0], {%1, %2};" :: "l"(p), "l"(a), "l"(b) : "memory");
}

__global__ __launch_bounds__(512, 1)
void snn_r15(const float* __restrict__ image,
             const float* __restrict__ W0,
             float* __restrict__ out)
{
    const int tid   = threadIdx.x;
    const int lane  = tid & 31;
    const int warp  = tid >> 5;
    const int group = warp >> 2;         // neuron slot, 0..3
    const int wing  = warp & 3;
    const int n     = blockIdx.x * NPB + group;
    const int barid = group + 1;

    const int  c0  = (wing << 5) + lane;
    const int  c1  = c0 + 128;
    const bool k1v = (c1 < CHUNKS);

    const float4 f4z = make_float4(0.f, 0.f, 0.f, 0.f);
    const u64 AP2 = pk2(A_PLUS, A_PLUS);
    const u64 BP2 = pk2(BETA_PLUS, BETA_PLUS);

    u64 w01[KMAX], w23[KMAX], pre01[KMAX], pre23[KMAX];
    u64 xc01[KMAX], xc23[KMAX], xn01[KMAX], xn23[KMAX];

    {   // load W row (packed)
        const float4* wrow = reinterpret_cast<const float4*>(W0) + (size_t)n * CHUNKS;
        float4 t0 = __ldg(wrow + c0);
        float4 t1 = k1v ? __ldg(wrow + c1) : f4z;
        w01[0] = pk2(t0.x, t0.y);  w23[0] = pk2(t0.z, t0.w);
        w01[1] = pk2(t1.x, t1.y);  w23[1] = pk2(t1.z, t1.w);
    }
    #pragma unroll
    for (int k = 0; k < KMAX; ++k) { pre01[k] = 0ull; pre23[k] = 0ull; }

    {   // prefetch x_0, x_1 (packed)
        const float4* xr = reinterpret_cast<const float4*>(image);
        float4 a0 = __ldg(xr + c0);
        float4 a1 = k1v ? __ldg(xr + c1) : f4z;
        float4 b0 = __ldg(xr + CHUNKS + c0);
        float4 b1 = k1v ? __ldg(xr + CHUNKS + c1) : f4z;
        xc01[0] = pk2(a0.x, a0.y); xc23[0] = pk2(a0.z, a0.w);
        xc01[1] = pk2(a1.x, a1.y); xc23[1] = pk2(a1.z, a1.w);
        xn01[0] = pk2(b0.x, b0.y); xn23[0] = pk2(b0.z, b0.w);
        xn01[1] = pk2(b1.x, b1.y); xn23[1] = pk2(b1.z, b1.w);
    }
    const float4* xpf = reinterpret_cast<const float4*>(image) + 2 * (size_t)CHUNKS;

    // ---- prologue: per-lane partial of W0 . x_0 ----
    float p;
    {
        u64 m01 = ffma2(w01[0], xc01[0], 0ull);
        m01     = ffma2(w01[1], xc01[1], m01);
        u64 m23 = ffma2(w23[0], xc23[0], 0ull);
        m23     = ffma2(w23[1], xc23[1], m23);
        float aa, ab, ac, ad;
        upk2(m01, aa, ab); upk2(m23, ac, ad);
        p = (aa + ab) + (ac + ad);
    }

    // 16 octet-partials per neuron (wing*4 + octet), double buffered.
    __shared__ float part[2][NPB][16];

    float syn = 0.f, mem = 0.f, spk_prev = 0.f, post = 0.f;

    float* __restrict__ spkrec  = out + (size_t)T_STEPS * N_NEUR * D_IN;
    float* __restrict__ memrec  = spkrec  + T_STEPS * N_NEUR;
    float* __restrict__ synrec  = memrec  + T_STEPS * N_NEUR;
    float* __restrict__ postrec = synrec  + T_STEPS * N_NEUR;

    float4* wptr = reinterpret_cast<float4*>(out) + (size_t)n * CHUNKS;
    int sidx = n;

    #pragma unroll 2
    for (int t = 0; t < T_STEPS; ++t) {
        const int buf = t & 1;

        // ---- (1) 3-shfl butterfly -> octet partials on lanes 0,8,16,24 ----
        float r = p;
        r += __shfl_xor_sync(0xffffffffu, r, 1);
        r += __shfl_xor_sync(0xffffffffu, r, 2);
        r += __shfl_xor_sync(0xffffffffu, r, 4);
        if ((lane & 7) == 0)
            part[buf][group][(wing << 2) + (lane >> 3)] = r;

        // ---- (2) pre-barrier LIF precompute (off the critical chain) ----
        const float synb  = ALPHA * syn;
        const float base  = fmaf(BETA, mem, synb - spk_prev * THRESHOLD);
        const float post0 = BETA_MINUS * post;
        const float post1 = fmaf(BETA_MINUS, post, 1.0f);
        const float am0   = -(A_MINUS * post0);
        const float am1   = -(A_MINUS * post1);

        neuron_bar(barid);

        // ---- I: 4 independent broadcast LDS.128 + add tree ----
        const float* pb = part[buf][group];
        const float4 q0 = *reinterpret_cast<const float4*>(pb + 0);
        const float4 q1 = *reinterpret_cast<const float4*>(pb + 4);
        const float4 q2 = *reinterpret_cast<const float4*>(pb + 8);
        const float4 q3 = *reinterpret_cast<const float4*>(pb + 12);
        const float s0 = (q0.x + q0.y) + (q0.z + q0.w);
        const float s1 = (q1.x + q1.y) + (q1.z + q1.w);
        const float s2 = (q2.x + q2.y) + (q2.z + q2.w);
        const float s3 = (q3.x + q3.y) + (q3.z + q3.w);
        const float I  = (s0 + s1) + (s2 + s3);

        // ---- short post-barrier LIF: FADD -> setp -> selects ----
        syn = synb + I;
        mem = base + I;
        const bool  spkb = (mem > THRESHOLD);
        const float spk  = spkb ? 1.0f : 0.0f;
        post = spkb ? post1 : post0;
        const float am   = spkb ? am1 : am0;
        const u64   ap2  = spkb ? AP2 : 0ull;

        // ---- STDP update + store W_rec[t]; fused next dot ----
        u64 da = 0ull, db = 0ull;
        #pragma unroll
        for (int k = 0; k < KMAX; ++k) {
            const bool act = (k == 0) || k1v;
            const int  c   = (k == 0) ? c0 : c1;

            const u64 t01 = ffma2(ap2, pre01[k], w01[k]);
            const u64 t23 = ffma2(ap2, pre23[k], w23[k]);
            float tx, ty, tz, tw, xx, xy, xz, xw;
            upk2(t01, tx, ty); upk2(t23, tz, tw);
            upk2(xc01[k], xx, xy); upk2(xc23[k], xz, xw);
            w01[k] = pk2(__saturatef(fmaf(am, xx, tx)),
                         __saturatef(fmaf(am, xy, ty)));
            w23[k] = pk2(__saturatef(fmaf(am, xz, tz)),
                         __saturatef(fmaf(am, xw, tw)));
            if (act) stg_cs_v2b64(wptr + c, w01[k], w23[k]);

            // fused dot for step t+1: W(t) . x_{t+1}
            da = ffma2(w01[k], xn01[k], da);
            db = ffma2(w23[k], xn23[k], db);

            // pre-trace recurrence (uses x_t)
            pre01[k] = ffma2(BP2, pre01[k], xc01[k]);
            pre23[k] = ffma2(BP2, pre23[k], xc23[k]);

            // rotate double buffer; prefetch x_{t+2}
            xc01[k] = xn01[k]; xc23[k] = xn23[k];
            if (act && (t + 2 < T_STEPS)) {
                float4 xt = __ldg(xpf + c);
                xn01[k] = pk2(xt.x, xt.y);
                xn23[k] = pk2(xt.z, xt.w);
            }
        }
        {
            float aa, ab, ac, ad;
            upk2(da, aa, ab); upk2(db, ac, ad);
            p = (aa + ab) + (ac + ad);
        }

        // ---- scalar records (one thread per neuron) ----
        if (wing == 0 && lane == 0) {
            spkrec[sidx]  = spk;
            memrec[sidx]  = mem;
            synrec[sidx]  = syn;
            postrec[sidx] = post;
        }

        spk_prev = spk;
        wptr += (size_t)N_NEUR * CHUNKS;
        xpf  += CHUNKS;
        sidx += N_NEUR;
    }
}

extern "C" void kernel_launch(void* const* d_in, const int* in_sizes, int n_in,
                              void* d_out, int out_size)
{
    const float* image = (const float*)d_in[0];  // [256, 784] f32
    const float* W     = (const float*)d_in[1];  // [512, 784] f32
    float* out = (float*)d_out;
    (void)in_sizes; (void)n_in; (void)out_size;
    snn_r15<<<N_NEUR / NPB, NPB * WPN * 32>>>(image, W, out);
}